// round 4
// baseline (speedup 1.0000x reference)
#include <cuda_runtime.h>

#define N_NODES 100000
#define N_EDGES 3200000
#define F 64

// ---------------- scratch (device globals; device-side references only) ----------
__device__ int   g_is64;                 // 1 if edge_index is int64, 0 if int32
__device__ int   g_count[N_NODES];
__device__ int   g_off[N_NODES + 1];
__device__ int   g_cursor[N_NODES];
__device__ float g_dinv[N_NODES];
__device__ int   g_srcs[N_EDGES];
__device__ float g_bufA[N_NODES * F];    // transform output  (agg input)
__device__ float g_bufB[N_NODES * F];    // aggregation output

// ---------------- dtype detection ----------------
// If edge_index is int64 (values < N_NODES), the high 32-bit word of every
// element is 0. For int32 data, odd int32 positions hold real node ids.
__global__ void k_detect(const int* __restrict__ ei32) {
    if (threadIdx.x == 0) {
        int any = 0;
        for (int i = 0; i < 64; i++) any |= ei32[2 * i + 1];
        g_is64 = (any == 0) ? 1 : 0;
    }
}

__device__ __forceinline__ int load_src(const int* ei32, int e) {
    return g_is64 ? ei32[2 * e] : ei32[e];
}
__device__ __forceinline__ int load_dst(const int* ei32, int e) {
    return g_is64 ? ei32[2 * (N_EDGES + e)] : ei32[N_EDGES + e];
}

// ---------------- kernels ----------------

__global__ void k_zero() {
    int i = blockIdx.x * blockDim.x + threadIdx.x;
    if (i < N_NODES) g_count[i] = 0;
}

__global__ void k_count(const int* __restrict__ ei32) {
    int e = blockIdx.x * blockDim.x + threadIdx.x;
    if (e < N_EDGES) {
        int d = load_dst(ei32, e);
        if ((unsigned)d < N_NODES) atomicAdd(&g_count[d], 1);
    }
}

__global__ void k_dinv() {
    int i = blockIdx.x * blockDim.x + threadIdx.x;
    if (i < N_NODES) g_dinv[i] = rsqrtf((float)g_count[i] + 1.0f);  // +1 self-loop
}

// Single-block exclusive scan over g_count -> g_off / g_cursor
__global__ void k_scan() {
    __shared__ int sums[1024];
    int t = threadIdx.x;
    const int CH = (N_NODES + 1023) / 1024;
    int lo = t * CH; if (lo > N_NODES) lo = N_NODES;
    int hi = lo + CH; if (hi > N_NODES) hi = N_NODES;
    int s = 0;
    for (int i = lo; i < hi; i++) s += g_count[i];
    sums[t] = s;
    __syncthreads();
    for (int off = 1; off < 1024; off <<= 1) {
        int v = (t >= off) ? sums[t - off] : 0;
        __syncthreads();
        sums[t] += v;
        __syncthreads();
    }
    int run = (t == 0) ? 0 : sums[t - 1];
    for (int i = lo; i < hi; i++) {
        int c = g_count[i];
        g_off[i] = run;
        g_cursor[i] = run;
        run += c;
    }
    if (t == 1023) g_off[N_NODES] = run;
}

__global__ void k_scatter(const int* __restrict__ ei32) {
    int e = blockIdx.x * blockDim.x + threadIdx.x;
    if (e < N_EDGES) {
        int s = load_src(ei32, e);
        int d = load_dst(ei32, e);
        if ((unsigned)d < N_NODES && (unsigned)s < N_NODES) {
            int pos = atomicAdd(&g_cursor[d], 1);
            g_srcs[pos] = s;
        }
    }
}

// bufA = x @ W1   (x: [N,22], W1: [22,64])
__global__ void k_gemm1(const float* __restrict__ x, const float* __restrict__ W1) {
    __shared__ float W1s[22 * 64];
    __shared__ float xs[4 * 22];
    int t = threadIdx.x;
    for (int i = t; i < 22 * 64; i += 256) W1s[i] = W1[i];
    int nodeblk = blockIdx.x * 4;
    for (int i = t; i < 4 * 22; i += 256) {
        int n = nodeblk + i / 22;
        xs[i] = (n < N_NODES) ? x[(size_t)n * 22 + (i % 22)] : 0.f;
    }
    __syncthreads();
    int r = t >> 6, j = t & 63;
    int node = nodeblk + r;
    if (node >= N_NODES) return;
    float acc = 0.f;
#pragma unroll
    for (int k = 0; k < 22; k++) acc += xs[r * 22 + k] * W1s[k * 64 + j];
    g_bufA[node * 64 + j] = acc;
}

// bufB[d] = bufA[d]*dinv[d]^2 + sum_{e in CSR(d)} bufA[src_e]*dinv[src_e]*dinv[d]
// one warp per dst node; float2 per lane covers 64 features
__global__ void k_agg() {
    int w = (blockIdx.x * blockDim.x + threadIdx.x) >> 5;
    int lane = threadIdx.x & 31;
    if (w >= N_NODES) return;
    float di = g_dinv[w];
    const float2* __restrict__ h2 = (const float2*)g_bufA;
    float2 v = h2[w * 32 + lane];
    float self = di * di;
    float2 acc;
    acc.x = v.x * self;
    acc.y = v.y * self;
    int lo = g_off[w], hi = g_off[w + 1];
    for (int base = lo; base < hi; base += 32) {
        int idx = base + lane;
        int s = (idx < hi) ? g_srcs[idx] : 0;
        float dv = (idx < hi) ? g_dinv[s] : 0.f;
        int nb = min(32, hi - base);
        for (int j = 0; j < nb; j++) {
            int sj = __shfl_sync(0xffffffffu, s, j);
            float nj = __shfl_sync(0xffffffffu, dv, j) * di;
            float2 hv = h2[sj * 32 + lane];
            acc.x += hv.x * nj;
            acc.y += hv.y * nj;
        }
    }
    ((float2*)g_bufB)[w * 32 + lane] = acc;
}

// bufA = relu(bufB + b1) @ W2
__global__ void k_xform2(const float* __restrict__ b1, const float* __restrict__ W2) {
    __shared__ float W2s[64 * 64];
    __shared__ float ts[4 * 64];
    int t = threadIdx.x;
    for (int i = t; i < 64 * 64; i += 256) W2s[i] = W2[i];
    int nb = blockIdx.x * 4;
    int r = t >> 6, j = t & 63;
    int node = nb + r;
    if (node < N_NODES) {
        float v = g_bufB[node * 64 + j] + b1[j];
        ts[r * 64 + j] = fmaxf(v, 0.f);
    }
    __syncthreads();
    if (node >= N_NODES) return;
    float acc = 0.f;
#pragma unroll
    for (int k = 0; k < 64; k++) acc += ts[r * 64 + k] * W2s[k * 64 + j];
    g_bufA[node * 64 + j] = acc;
}

// out = relu(bufB + b2) @ Wf + bf   (warp per node)
__global__ void k_final(const float* __restrict__ b2, const float* __restrict__ Wf,
                        const float* __restrict__ bf, float* __restrict__ out) {
    int w = (blockIdx.x * blockDim.x + threadIdx.x) >> 5;
    int lane = threadIdx.x & 31;
    if (w >= N_NODES) return;
    float a = fmaxf(g_bufB[w * 64 + lane] + b2[lane], 0.f) * Wf[lane];
    float b = fmaxf(g_bufB[w * 64 + lane + 32] + b2[lane + 32], 0.f) * Wf[lane + 32];
    float s = a + b;
#pragma unroll
    for (int off = 16; off; off >>= 1) s += __shfl_xor_sync(0xffffffffu, s, off);
    if (lane == 0) out[w] = s + bf[0];
}

// ---------------- launch ----------------

extern "C" void kernel_launch(void* const* d_in, const int* in_sizes, int n_in,
                              void* d_out, int out_size) {
    const float* x   = (const float*)d_in[0];
    const int*   ei  = (const int*)d_in[1];   // int32 or int64 (detected on device)
    const float* W1  = (const float*)d_in[2];
    const float* b1  = (const float*)d_in[3];
    const float* W2  = (const float*)d_in[4];
    const float* b2  = (const float*)d_in[5];
    const float* Wf  = (const float*)d_in[6];
    const float* bf  = (const float*)d_in[7];
    float* out = (float*)d_out;

    const int TB = 256;
    int gN = (N_NODES + TB - 1) / TB;
    int gE = (N_EDGES + TB - 1) / TB;
    int gW = (N_NODES * 32 + TB - 1) / TB;   // warp-per-node grids
    int gT = (N_NODES + 3) / 4;              // 4 nodes per block transforms

    // CSR build (per-launch; deterministic)
    k_detect<<<1, 32>>>(ei);
    k_zero<<<gN, TB>>>();
    k_count<<<gE, TB>>>(ei);
    k_dinv<<<gN, TB>>>();
    k_scan<<<1, 1024>>>();
    k_scatter<<<gE, TB>>>(ei);

    // layer 1
    k_gemm1<<<gT, TB>>>(x, W1);      // bufA = x@W1
    k_agg<<<gW, TB>>>();             // bufB = agg(bufA)

    // layer 2
    k_xform2<<<gT, TB>>>(b1, W2);    // bufA = relu(bufB+b1)@W2
    k_agg<<<gW, TB>>>();             // bufB = agg(bufA)

    // head
    k_final<<<gW, TB>>>(b2, Wf, bf, out);
}

// round 5
// speedup vs baseline: 1.0732x; 1.0732x over previous
#include <cuda_runtime.h>

#define N_NODES 100000
#define N_EDGES 3200000

// ---------------- scratch (device globals; device-side references only) ----------
__device__ int   g_is64;                 // 1 if edge_index is int64, 0 if int32
__device__ int   g_count[N_NODES];
__device__ int   g_off[N_NODES + 1];
__device__ int   g_cursor[N_NODES];
__device__ float g_dinv[N_NODES];
__device__ int2  g_edge[N_EDGES];        // {src, float_bits(dinv[src])}
__device__ float g_xpad[N_NODES * 32];   // x padded 22->32 (one 128B line per node)
__device__ float g_aggX[N_NODES * 32];   // aggregated raw features
__device__ float g_h64[N_NODES * 64];    // relu(aggX@W1+b1)@W2  (layer-2 agg input)

// ---------------- dtype detection ----------------
__global__ void k_detect(const int* __restrict__ ei32) {
    if (threadIdx.x == 0) {
        int any = 0;
        for (int i = 0; i < 64; i++) any |= ei32[2 * i + 1];
        g_is64 = (any == 0) ? 1 : 0;
    }
}
__device__ __forceinline__ int load_src(const int* ei32, int e) {
    return g_is64 ? ei32[2 * e] : ei32[e];
}
__device__ __forceinline__ int load_dst(const int* ei32, int e) {
    return g_is64 ? ei32[2 * (N_EDGES + e)] : ei32[N_EDGES + e];
}

// ---------------- CSR build ----------------
__global__ void k_zero() {
    int i = blockIdx.x * blockDim.x + threadIdx.x;
    if (i < N_NODES) g_count[i] = 0;
}

__global__ void k_count(const int* __restrict__ ei32) {
    int e = blockIdx.x * blockDim.x + threadIdx.x;
    if (e < N_EDGES) {
        int d = load_dst(ei32, e);
        if ((unsigned)d < N_NODES) atomicAdd(&g_count[d], 1);
    }
}

__global__ void k_dinv() {
    int i = blockIdx.x * blockDim.x + threadIdx.x;
    if (i < N_NODES) g_dinv[i] = rsqrtf((float)g_count[i] + 1.0f);  // +1 self-loop
}

__global__ void k_scan() {
    __shared__ int sums[1024];
    int t = threadIdx.x;
    const int CH = (N_NODES + 1023) / 1024;
    int lo = t * CH; if (lo > N_NODES) lo = N_NODES;
    int hi = lo + CH; if (hi > N_NODES) hi = N_NODES;
    int s = 0;
    for (int i = lo; i < hi; i++) s += g_count[i];
    sums[t] = s;
    __syncthreads();
    for (int off = 1; off < 1024; off <<= 1) {
        int v = (t >= off) ? sums[t - off] : 0;
        __syncthreads();
        sums[t] += v;
        __syncthreads();
    }
    int run = (t == 0) ? 0 : sums[t - 1];
    for (int i = lo; i < hi; i++) {
        int c = g_count[i];
        g_off[i] = run;
        g_cursor[i] = run;
        run += c;
    }
    if (t == 1023) g_off[N_NODES] = run;
}

__global__ void k_scatter(const int* __restrict__ ei32) {
    int e = blockIdx.x * blockDim.x + threadIdx.x;
    if (e < N_EDGES) {
        int s = load_src(ei32, e);
        int d = load_dst(ei32, e);
        if ((unsigned)d < N_NODES && (unsigned)s < N_NODES) {
            int pos = atomicAdd(&g_cursor[d], 1);
            g_edge[pos] = make_int2(s, __float_as_int(g_dinv[s]));
        }
    }
}

// ---------------- features ----------------
// pad x [N,22] -> g_xpad [N,32]
__global__ void k_pad(const float* __restrict__ x) {
    int i = blockIdx.x * blockDim.x + threadIdx.x;
    if (i < N_NODES * 32) {
        int n = i >> 5, c = i & 31;
        g_xpad[i] = (c < 22) ? x[n * 22 + c] : 0.f;
    }
}

// aggX[d] = xpad[d]*dinv[d]^2 + sum_e xpad[src_e]*dinv[src_e]*dinv[d]
// one warp per dst node; 1 float per lane (one 128B line per edge)
__global__ void k_agg1() {
    int w = (blockIdx.x * blockDim.x + threadIdx.x) >> 5;
    int lane = threadIdx.x & 31;
    if (w >= N_NODES) return;
    float di = g_dinv[w];
    float acc = g_xpad[w * 32 + lane] * di * di;
    int lo = g_off[w], hi = g_off[w + 1];
    int nfull = (hi - lo) & ~31;
    int base = lo;
    for (; base < lo + nfull; base += 32) {
        int2 ed = g_edge[base + lane];
#pragma unroll
        for (int j = 0; j < 32; j++) {
            int   sj = __shfl_sync(0xffffffffu, ed.x, j);
            float nj = __int_as_float(__shfl_sync(0xffffffffu, ed.y, j)) * di;
            acc += g_xpad[sj * 32 + lane] * nj;
        }
    }
    int rem = hi - base;
    if (rem > 0) {
        int idx = base + lane;
        int2 ed = (idx < hi) ? g_edge[idx] : make_int2(0, 0);
        for (int j = 0; j < rem; j++) {
            int   sj = __shfl_sync(0xffffffffu, ed.x, j);
            float nj = __int_as_float(__shfl_sync(0xffffffffu, ed.y, j)) * di;
            acc += g_xpad[sj * 32 + lane] * nj;
        }
    }
    g_aggX[w * 32 + lane] = acc;
}

// h64 = relu(aggX[:, :22] @ W1 + b1) @ W2   (4 nodes per 256-thread block)
__global__ void k_xform12(const float* __restrict__ W1, const float* __restrict__ b1,
                          const float* __restrict__ W2) {
    __shared__ float W1s[22 * 64];
    __shared__ float W2s[64 * 64];
    __shared__ float h1s[4 * 64];
    __shared__ float as[4 * 22];
    int t = threadIdx.x;
    for (int i = t; i < 22 * 64; i += 256) W1s[i] = W1[i];
    for (int i = t; i < 64 * 64; i += 256) W2s[i] = W2[i];
    int nb = blockIdx.x * 4;
    for (int i = t; i < 4 * 22; i += 256) {
        int n = nb + i / 22;
        as[i] = (n < N_NODES) ? g_aggX[n * 32 + (i % 22)] : 0.f;
    }
    __syncthreads();
    int r = t >> 6, j = t & 63;
    int node = nb + r;
    float a = 0.f;
#pragma unroll
    for (int k = 0; k < 22; k++) a += as[r * 22 + k] * W1s[k * 64 + j];
    h1s[r * 64 + j] = fmaxf(a + b1[j], 0.f);
    __syncthreads();
    float acc = 0.f;
#pragma unroll
    for (int k = 0; k < 64; k++) acc += h1s[r * 64 + k] * W2s[k * 64 + j];
    if (node < N_NODES) g_h64[node * 64 + j] = acc;
}

// layer-2 aggregation fused with final head:
// out[d] = relu(agg2[d] + b2) . Wf + bf     (warp per node, float2 per lane)
__global__ void k_agg2f(const float* __restrict__ b2, const float* __restrict__ Wf,
                        const float* __restrict__ bf, float* __restrict__ out) {
    int w = (blockIdx.x * blockDim.x + threadIdx.x) >> 5;
    int lane = threadIdx.x & 31;
    if (w >= N_NODES) return;
    float di = g_dinv[w];
    const float2* __restrict__ h2 = (const float2*)g_h64;
    float2 v = h2[w * 32 + lane];
    float self = di * di;
    float2 acc;
    acc.x = v.x * self;
    acc.y = v.y * self;
    int lo = g_off[w], hi = g_off[w + 1];
    int nfull = (hi - lo) & ~31;
    int base = lo;
    for (; base < lo + nfull; base += 32) {
        int2 ed = g_edge[base + lane];
#pragma unroll
        for (int j = 0; j < 32; j++) {
            int   sj = __shfl_sync(0xffffffffu, ed.x, j);
            float nj = __int_as_float(__shfl_sync(0xffffffffu, ed.y, j)) * di;
            float2 hv = h2[sj * 32 + lane];
            acc.x += hv.x * nj;
            acc.y += hv.y * nj;
        }
    }
    int rem = hi - base;
    if (rem > 0) {
        int idx = base + lane;
        int2 ed = (idx < hi) ? g_edge[idx] : make_int2(0, 0);
        for (int j = 0; j < rem; j++) {
            int   sj = __shfl_sync(0xffffffffu, ed.x, j);
            float nj = __int_as_float(__shfl_sync(0xffffffffu, ed.y, j)) * di;
            float2 hv = h2[sj * 32 + lane];
            acc.x += hv.x * nj;
            acc.y += hv.y * nj;
        }
    }
    // fused head: features 2*lane, 2*lane+1
    float r0 = fmaxf(acc.x + b2[2 * lane], 0.f) * Wf[2 * lane];
    float r1 = fmaxf(acc.y + b2[2 * lane + 1], 0.f) * Wf[2 * lane + 1];
    float s = r0 + r1;
#pragma unroll
    for (int off = 16; off; off >>= 1) s += __shfl_xor_sync(0xffffffffu, s, off);
    if (lane == 0) out[w] = s + bf[0];
}

// ---------------- launch ----------------
extern "C" void kernel_launch(void* const* d_in, const int* in_sizes, int n_in,
                              void* d_out, int out_size) {
    const float* x   = (const float*)d_in[0];
    const int*   ei  = (const int*)d_in[1];
    const float* W1  = (const float*)d_in[2];
    const float* b1  = (const float*)d_in[3];
    const float* W2  = (const float*)d_in[4];
    const float* b2  = (const float*)d_in[5];
    const float* Wf  = (const float*)d_in[6];
    const float* bf  = (const float*)d_in[7];
    float* out = (float*)d_out;

    const int TB = 256;
    int gN = (N_NODES + TB - 1) / TB;
    int gE = (N_EDGES + TB - 1) / TB;
    int gW = (N_NODES * 32 + TB - 1) / TB;   // warp-per-node grids
    int gP = (N_NODES * 32 + TB - 1) / TB;
    int gT = (N_NODES + 3) / 4;

    // CSR build
    k_detect<<<1, 32>>>(ei);
    k_zero<<<gN, TB>>>();
    k_count<<<gE, TB>>>(ei);
    k_dinv<<<gN, TB>>>();
    k_scan<<<1, 1024>>>();
    k_scatter<<<gE, TB>>>(ei);

    // layer 1 (aggregate raw features, transform after)
    k_pad<<<gP, TB>>>(x);
    k_agg1<<<gW, TB>>>();            // aggX = agg(xpad)
    k_xform12<<<gT, TB>>>(W1, b1, W2); // h64 = relu(aggX@W1+b1)@W2

    // layer 2 + head (fused)
    k_agg2f<<<gW, TB>>>(b2, Wf, bf, out);
}

// round 6
// speedup vs baseline: 1.7909x; 1.6688x over previous
#include <cuda_runtime.h>
#include <cuda_fp16.h>

#define N_NODES 100000
#define N_EDGES 3200000
#define NB_SCAN 391            // ceil(N_NODES/256)

// ---------------- scratch ----------------
__device__ int    g_is64;
__device__ int    g_count[N_NODES];
__device__ int    g_part[NB_SCAN];
__device__ int    g_partoff[NB_SCAN];
__device__ int    g_off[N_NODES + 1];
__device__ int    g_cursor[N_NODES];
__device__ float  g_dinv[N_NODES];
__device__ int2   g_edge[N_EDGES];       // {src, float_bits(dinv[src])}
__device__ float  g_xpad[N_NODES * 32];  // x padded 22->32
__device__ float  g_aggX[N_NODES * 32];  // aggregated raw features
__device__ __half g_h16[N_NODES * 64];   // layer-2 agg input (fp16, 128B/node)

// ---------------- helpers ----------------
__device__ __forceinline__ int load_src(const int* ei32, int e) {
    return g_is64 ? ei32[2 * e] : ei32[e];
}
__device__ __forceinline__ int load_dst(const int* ei32, int e) {
    return g_is64 ? ei32[2 * (N_EDGES + e)] : ei32[N_EDGES + e];
}

// init: pad x -> xpad, zero counts, detect dtype
__global__ void k_init(const float* __restrict__ x, const int* __restrict__ ei32) {
    int i = blockIdx.x * blockDim.x + threadIdx.x;
    if (i < N_NODES * 32) {
        int n = i >> 5, c = i & 31;
        g_xpad[i] = (c < 22) ? x[n * 22 + c] : 0.f;
    }
    if (i < N_NODES) g_count[i] = 0;
    if (i < 32) {  // warp 0 of block 0: dtype detect
        int any = ei32[2 * i + 1] | ei32[2 * (i + 32) + 1];
        for (int off = 16; off; off >>= 1) any |= __shfl_xor_sync(0xffffffffu, any, off);
        if (i == 0) g_is64 = (any == 0) ? 1 : 0;
    }
}

__global__ void k_count(const int* __restrict__ ei32) {
    int e = blockIdx.x * blockDim.x + threadIdx.x;
    if (e < N_EDGES) {
        int d = load_dst(ei32, e);
        if ((unsigned)d < N_NODES) atomicAdd(&g_count[d], 1);
    }
}

// scan phase 1: per-block partial sums + dinv
__global__ void k_scan1() {
    __shared__ int red[256];
    int t = threadIdx.x;
    int i = blockIdx.x * 256 + t;
    int c = (i < N_NODES) ? g_count[i] : 0;
    if (i < N_NODES) g_dinv[i] = rsqrtf((float)c + 1.0f);  // +1 self-loop
    red[t] = c;
    __syncthreads();
    for (int off = 128; off; off >>= 1) {
        if (t < off) red[t] += red[t + off];
        __syncthreads();
    }
    if (t == 0) g_part[blockIdx.x] = red[0];
}

// scan phase 2: single block scans NB_SCAN partials (exclusive)
__global__ void k_scan2() {
    __shared__ int s[512];
    int t = threadIdx.x;
    int v = (t < NB_SCAN) ? g_part[t] : 0;
    s[t] = v;
    __syncthreads();
    for (int off = 1; off < 512; off <<= 1) {
        int u = (t >= off) ? s[t - off] : 0;
        __syncthreads();
        s[t] += u;
        __syncthreads();
    }
    if (t < NB_SCAN) g_partoff[t] = s[t] - v;  // exclusive
    if (t == 511) g_off[N_NODES] = s[511];
}

// scan phase 3: block-local exclusive scan + partial offset -> g_off/g_cursor
__global__ void k_scan3() {
    __shared__ int s[256];
    int t = threadIdx.x;
    int i = blockIdx.x * 256 + t;
    int c = (i < N_NODES) ? g_count[i] : 0;
    s[t] = c;
    __syncthreads();
    for (int off = 1; off < 256; off <<= 1) {
        int u = (t >= off) ? s[t - off] : 0;
        __syncthreads();
        s[t] += u;
        __syncthreads();
    }
    if (i < N_NODES) {
        int excl = s[t] - c + g_partoff[blockIdx.x];
        g_off[i] = excl;
        g_cursor[i] = excl;
    }
}

__global__ void k_scatter(const int* __restrict__ ei32) {
    int e = blockIdx.x * blockDim.x + threadIdx.x;
    if (e < N_EDGES) {
        int s = load_src(ei32, e);
        int d = load_dst(ei32, e);
        if ((unsigned)d < N_NODES && (unsigned)s < N_NODES) {
            int pos = atomicAdd(&g_cursor[d], 1);
            g_edge[pos] = make_int2(s, __float_as_int(g_dinv[s]));
        }
    }
}

// aggX[d] = xpad[d]*dinv^2 + sum_e xpad[src]*dinv[src]*dinv[d]; warp per node
__global__ void k_agg1() {
    int w = (blockIdx.x * blockDim.x + threadIdx.x) >> 5;
    int lane = threadIdx.x & 31;
    if (w >= N_NODES) return;
    float di = g_dinv[w];
    float acc = g_xpad[w * 32 + lane] * di * di;
    int lo = g_off[w], hi = g_off[w + 1];
    int base = lo;
    int nfull = (hi - lo) & ~31;
    for (; base < lo + nfull; base += 32) {
        int2 ed = g_edge[base + lane];
#pragma unroll
        for (int j = 0; j < 32; j++) {
            int   sj = __shfl_sync(0xffffffffu, ed.x, j);
            float nj = __int_as_float(__shfl_sync(0xffffffffu, ed.y, j)) * di;
            acc += g_xpad[sj * 32 + lane] * nj;
        }
    }
    int rem = hi - base;
    if (rem > 0) {
        int idx = base + lane;
        int2 ed = (idx < hi) ? g_edge[idx] : make_int2(0, 0);
        for (int j = 0; j < rem; j++) {
            int   sj = __shfl_sync(0xffffffffu, ed.x, j);
            float nj = __int_as_float(__shfl_sync(0xffffffffu, ed.y, j)) * di;
            acc += g_xpad[sj * 32 + lane] * nj;
        }
    }
    g_aggX[w * 32 + lane] = acc;
}

// h16 = fp16( relu(aggX[:, :22]@W1 + b1) @ W2 ); 16 nodes per 256-thread block
__global__ void k_xform12(const float* __restrict__ W1, const float* __restrict__ b1,
                          const float* __restrict__ W2) {
    __shared__ float W1s[22 * 64];
    __shared__ float W2s[64 * 64];
    __shared__ float h1s[4 * 64];
    __shared__ float as[4 * 22];
    int t = threadIdx.x;
    for (int i = t; i < 22 * 64; i += 256) W1s[i] = W1[i];
    for (int i = t; i < 64 * 64; i += 256) W2s[i] = W2[i];
    int r = t >> 6, j = t & 63;
    float b1j = b1[j];
#pragma unroll
    for (int p = 0; p < 4; p++) {
        int nb = blockIdx.x * 16 + p * 4;
        __syncthreads();  // protects weights (p=0) / as,h1s reuse (p>0)
        for (int i = t; i < 4 * 22; i += 256) {
            int n = nb + i / 22;
            as[i] = (n < N_NODES) ? g_aggX[n * 32 + (i % 22)] : 0.f;
        }
        __syncthreads();
        float a = 0.f;
#pragma unroll
        for (int k = 0; k < 22; k++) a += as[r * 22 + k] * W1s[k * 64 + j];
        h1s[r * 64 + j] = fmaxf(a + b1j, 0.f);
        __syncthreads();
        float acc = 0.f;
#pragma unroll
        for (int k = 0; k < 64; k++) acc += h1s[r * 64 + k] * W2s[k * 64 + j];
        int node = nb + r;
        if (node < N_NODES) g_h16[node * 64 + j] = __float2half_rn(acc);
    }
}

// layer-2 agg (fp16 gather, one 128B line per edge) fused with head
__global__ void k_agg2f(const float* __restrict__ b2, const float* __restrict__ Wf,
                        const float* __restrict__ bf, float* __restrict__ out) {
    int w = (blockIdx.x * blockDim.x + threadIdx.x) >> 5;
    int lane = threadIdx.x & 31;
    if (w >= N_NODES) return;
    float di = g_dinv[w];
    const __half2* __restrict__ h2 = (const __half2*)g_h16;
    float2 v = __half22float2(h2[w * 32 + lane]);
    float self = di * di;
    float2 acc;
    acc.x = v.x * self;
    acc.y = v.y * self;
    int lo = g_off[w], hi = g_off[w + 1];
    int base = lo;
    int nfull = (hi - lo) & ~31;
    for (; base < lo + nfull; base += 32) {
        int2 ed = g_edge[base + lane];
#pragma unroll
        for (int j = 0; j < 32; j++) {
            int   sj = __shfl_sync(0xffffffffu, ed.x, j);
            float nj = __int_as_float(__shfl_sync(0xffffffffu, ed.y, j)) * di;
            float2 hv = __half22float2(h2[sj * 32 + lane]);
            acc.x += hv.x * nj;
            acc.y += hv.y * nj;
        }
    }
    int rem = hi - base;
    if (rem > 0) {
        int idx = base + lane;
        int2 ed = (idx < hi) ? g_edge[idx] : make_int2(0, 0);
        for (int j = 0; j < rem; j++) {
            int   sj = __shfl_sync(0xffffffffu, ed.x, j);
            float nj = __int_as_float(__shfl_sync(0xffffffffu, ed.y, j)) * di;
            float2 hv = __half22float2(h2[sj * 32 + lane]);
            acc.x += hv.x * nj;
            acc.y += hv.y * nj;
        }
    }
    float r0 = fmaxf(acc.x + b2[2 * lane], 0.f) * Wf[2 * lane];
    float r1 = fmaxf(acc.y + b2[2 * lane + 1], 0.f) * Wf[2 * lane + 1];
    float s = r0 + r1;
#pragma unroll
    for (int off = 16; off; off >>= 1) s += __shfl_xor_sync(0xffffffffu, s, off);
    if (lane == 0) out[w] = s + bf[0];
}

// ---------------- launch ----------------
extern "C" void kernel_launch(void* const* d_in, const int* in_sizes, int n_in,
                              void* d_out, int out_size) {
    const float* x   = (const float*)d_in[0];
    const int*   ei  = (const int*)d_in[1];
    const float* W1  = (const float*)d_in[2];
    const float* b1  = (const float*)d_in[3];
    const float* W2  = (const float*)d_in[4];
    const float* b2  = (const float*)d_in[5];
    const float* Wf  = (const float*)d_in[6];
    const float* bf  = (const float*)d_in[7];
    float* out = (float*)d_out;

    const int TB = 256;
    int gI = (N_NODES * 32 + TB - 1) / TB;
    int gE = (N_EDGES + TB - 1) / TB;
    int gW = (N_NODES * 32 + TB - 1) / TB;
    int gT = (N_NODES + 15) / 16;

    k_init<<<gI, TB>>>(x, ei);
    k_count<<<gE, TB>>>(ei);
    k_scan1<<<NB_SCAN, 256>>>();
    k_scan2<<<1, 512>>>();
    k_scan3<<<NB_SCAN, 256>>>();
    k_scatter<<<gE, TB>>>(ei);

    k_agg1<<<gW, TB>>>();
    k_xform12<<<gT, TB>>>(W1, b1, W2);
    k_agg2f<<<gW, TB>>>(b2, Wf, bf, out);
}

// round 7
// speedup vs baseline: 1.8304x; 1.0220x over previous
#include <cuda_runtime.h>
#include <cuda_fp16.h>

#define N_NODES 100000
#define N_EDGES 3200000
#define NB_SCAN 391            // ceil(N_NODES/256)

// ---------------- scratch ----------------
__device__ int    g_is64;
__device__ int    g_count[N_NODES];      // zero at start of every run (see k_scan3)
__device__ int    g_part[NB_SCAN];
__device__ int    g_partoff[NB_SCAN];
__device__ int    g_off[N_NODES + 1];
__device__ int    g_cursor[N_NODES];
__device__ float  g_dinv[N_NODES];
__device__ int2   g_edge[N_EDGES];       // {src, float_bits(dinv[src])}
__device__ __half g_x16[N_NODES * 32];   // x padded 22->32, fp16 (64B/node)
__device__ float  g_aggX[N_NODES * 32];  // aggregated raw features (fp32)
__device__ __half g_h16[N_NODES * 64];   // layer-2 agg input (fp16, 128B/node)

// ---------------- fused init: pad x, detect dtype, count degrees ----------------
// grid covers 3.2M threads == N_NODES*32 (pad) == N_EDGES (count). Counts were
// zeroed by the previous run's k_scan3 (BSS-zero on the very first run).
__global__ void k_initcount(const float* __restrict__ x, const int* __restrict__ ei32) {
    __shared__ int s_is64;
    int t = threadIdx.x;
    if (t < 32) {  // per-block dtype detect (no cross-block race; L2-broadcast reads)
        int any = ei32[2 * t + 1] | ei32[2 * (t + 32) + 1];
        for (int off = 16; off; off >>= 1) any |= __shfl_xor_sync(0xffffffffu, any, off);
        if (t == 0) {
            s_is64 = (any == 0) ? 1 : 0;
            if (blockIdx.x == 0) g_is64 = s_is64;   // for k_scatter
        }
    }
    int i = blockIdx.x * blockDim.x + t;
    if (i < N_NODES * 32) {
        int n = i >> 5, c = i & 31;
        g_x16[i] = __float2half_rn((c < 22) ? x[n * 22 + c] : 0.f);
    }
    __syncthreads();
    int is64 = s_is64;
    // i also indexes edges (same 3.2M range)
    int d = is64 ? ei32[2 * (N_EDGES + i)] : ei32[N_EDGES + i];
    if ((unsigned)d < N_NODES) atomicAdd(&g_count[d], 1);
}

// scan phase 1: per-block partial sums + dinv
__global__ void k_scan1() {
    __shared__ int red[256];
    int t = threadIdx.x;
    int i = blockIdx.x * 256 + t;
    int c = (i < N_NODES) ? g_count[i] : 0;
    if (i < N_NODES) g_dinv[i] = rsqrtf((float)c + 1.0f);  // +1 self-loop
    red[t] = c;
    __syncthreads();
    for (int off = 128; off; off >>= 1) {
        if (t < off) red[t] += red[t + off];
        __syncthreads();
    }
    if (t == 0) g_part[blockIdx.x] = red[0];
}

// scan phase 2: single block, warp-shuffle scan of NB_SCAN partials (exclusive)
__global__ void k_scan2() {
    __shared__ int wsum[16];
    int t = threadIdx.x;            // 512 threads
    int lane = t & 31, wid = t >> 5;
    int v = (t < NB_SCAN) ? g_part[t] : 0;
    int s = v;
#pragma unroll
    for (int off = 1; off < 32; off <<= 1) {
        int u = __shfl_up_sync(0xffffffffu, s, off);
        if (lane >= off) s += u;
    }
    if (lane == 31) wsum[wid] = s;
    __syncthreads();
    if (wid == 0) {
        int ws = (lane < 16) ? wsum[lane] : 0;
#pragma unroll
        for (int off = 1; off < 16; off <<= 1) {
            int u = __shfl_up_sync(0xffffffffu, ws, off);
            if (lane >= off) ws += u;
        }
        if (lane < 16) wsum[lane] = ws;
    }
    __syncthreads();
    int incl = s + (wid > 0 ? wsum[wid - 1] : 0);
    if (t < NB_SCAN) g_partoff[t] = incl - v;   // exclusive
    if (t == 511) g_off[N_NODES] = incl;
}

// scan phase 3: block-local exclusive scan + offset; RE-ZEROES g_count for next run
__global__ void k_scan3() {
    __shared__ int s[256];
    int t = threadIdx.x;
    int i = blockIdx.x * 256 + t;
    int c = (i < N_NODES) ? g_count[i] : 0;
    s[t] = c;
    __syncthreads();
    for (int off = 1; off < 256; off <<= 1) {
        int u = (t >= off) ? s[t - off] : 0;
        __syncthreads();
        s[t] += u;
        __syncthreads();
    }
    if (i < N_NODES) {
        int excl = s[t] - c + g_partoff[blockIdx.x];
        g_off[i] = excl;
        g_cursor[i] = excl;
        g_count[i] = 0;            // ready for next replay
    }
}

__global__ void k_scatter(const int* __restrict__ ei32) {
    int e = blockIdx.x * blockDim.x + threadIdx.x;
    if (e < N_EDGES) {
        int is64 = g_is64;
        int s = is64 ? ei32[2 * e] : ei32[e];
        int d = is64 ? ei32[2 * (N_EDGES + e)] : ei32[N_EDGES + e];
        if ((unsigned)d < N_NODES && (unsigned)s < N_NODES) {
            int pos = atomicAdd(&g_cursor[d], 1);
            g_edge[pos] = make_int2(s, __float_as_int(g_dinv[s]));
        }
    }
}

// aggX[d] = x16[d]*dinv^2 + sum_e x16[src]*dinv[src]*dinv[d]; warp per node,
// one __half per lane -> 64B per edge gather
__global__ void k_agg1() {
    int w = (blockIdx.x * blockDim.x + threadIdx.x) >> 5;
    int lane = threadIdx.x & 31;
    if (w >= N_NODES) return;
    float di = g_dinv[w];
    float acc = __half2float(g_x16[w * 32 + lane]) * di * di;
    int lo = g_off[w], hi = g_off[w + 1];
    int base = lo;
    int nfull = (hi - lo) & ~31;
    for (; base < lo + nfull; base += 32) {
        int2 ed = g_edge[base + lane];
#pragma unroll
        for (int j = 0; j < 32; j++) {
            int   sj = __shfl_sync(0xffffffffu, ed.x, j);
            float nj = __int_as_float(__shfl_sync(0xffffffffu, ed.y, j)) * di;
            acc += __half2float(g_x16[sj * 32 + lane]) * nj;
        }
    }
    int rem = hi - base;
    if (rem > 0) {
        int idx = base + lane;
        int2 ed = (idx < hi) ? g_edge[idx] : make_int2(0, 0);
        for (int j = 0; j < rem; j++) {
            int   sj = __shfl_sync(0xffffffffu, ed.x, j);
            float nj = __int_as_float(__shfl_sync(0xffffffffu, ed.y, j)) * di;
            acc += __half2float(g_x16[sj * 32 + lane]) * nj;
        }
    }
    g_aggX[w * 32 + lane] = acc;
}

// h16 = fp16( relu(aggX[:, :22]@W1 + b1) @ W2 ); 16 nodes per 256-thread block
__global__ void k_xform12(const float* __restrict__ W1, const float* __restrict__ b1,
                          const float* __restrict__ W2) {
    __shared__ float W1s[22 * 64];
    __shared__ float W2s[64 * 64];
    __shared__ float h1s[4 * 64];
    __shared__ float as[4 * 22];
    int t = threadIdx.x;
    for (int i = t; i < 22 * 64; i += 256) W1s[i] = W1[i];
    for (int i = t; i < 64 * 64; i += 256) W2s[i] = W2[i];
    int r = t >> 6, j = t & 63;
    float b1j = b1[j];
#pragma unroll
    for (int p = 0; p < 4; p++) {
        int nb = blockIdx.x * 16 + p * 4;
        __syncthreads();
        for (int i = t; i < 4 * 22; i += 256) {
            int n = nb + i / 22;
            as[i] = (n < N_NODES) ? g_aggX[n * 32 + (i % 22)] : 0.f;
        }
        __syncthreads();
        float a = 0.f;
#pragma unroll
        for (int k = 0; k < 22; k++) a += as[r * 22 + k] * W1s[k * 64 + j];
        h1s[r * 64 + j] = fmaxf(a + b1j, 0.f);
        __syncthreads();
        float acc = 0.f;
#pragma unroll
        for (int k = 0; k < 64; k++) acc += h1s[r * 64 + k] * W2s[k * 64 + j];
        int node = nb + r;
        if (node < N_NODES) g_h16[node * 64 + j] = __float2half_rn(acc);
    }
}

// layer-2 agg (fp16, 128B per edge) fused with head
__global__ void k_agg2f(const float* __restrict__ b2, const float* __restrict__ Wf,
                        const float* __restrict__ bf, float* __restrict__ out) {
    int w = (blockIdx.x * blockDim.x + threadIdx.x) >> 5;
    int lane = threadIdx.x & 31;
    if (w >= N_NODES) return;
    float di = g_dinv[w];
    const __half2* __restrict__ h2 = (const __half2*)g_h16;
    float2 v = __half22float2(h2[w * 32 + lane]);
    float self = di * di;
    float2 acc;
    acc.x = v.x * self;
    acc.y = v.y * self;
    int lo = g_off[w], hi = g_off[w + 1];
    int base = lo;
    int nfull = (hi - lo) & ~31;
    for (; base < lo + nfull; base += 32) {
        int2 ed = g_edge[base + lane];
#pragma unroll
        for (int j = 0; j < 32; j++) {
            int   sj = __shfl_sync(0xffffffffu, ed.x, j);
            float nj = __int_as_float(__shfl_sync(0xffffffffu, ed.y, j)) * di;
            float2 hv = __half22float2(h2[sj * 32 + lane]);
            acc.x += hv.x * nj;
            acc.y += hv.y * nj;
        }
    }
    int rem = hi - base;
    if (rem > 0) {
        int idx = base + lane;
        int2 ed = (idx < hi) ? g_edge[idx] : make_int2(0, 0);
        for (int j = 0; j < rem; j++) {
            int   sj = __shfl_sync(0xffffffffu, ed.x, j);
            float nj = __int_as_float(__shfl_sync(0xffffffffu, ed.y, j)) * di;
            float2 hv = __half22float2(h2[sj * 32 + lane]);
            acc.x += hv.x * nj;
            acc.y += hv.y * nj;
        }
    }
    float r0 = fmaxf(acc.x + b2[2 * lane], 0.f) * Wf[2 * lane];
    float r1 = fmaxf(acc.y + b2[2 * lane + 1], 0.f) * Wf[2 * lane + 1];
    float s = r0 + r1;
#pragma unroll
    for (int off = 16; off; off >>= 1) s += __shfl_xor_sync(0xffffffffu, s, off);
    if (lane == 0) out[w] = s + bf[0];
}

// ---------------- launch ----------------
extern "C" void kernel_launch(void* const* d_in, const int* in_sizes, int n_in,
                              void* d_out, int out_size) {
    const float* x   = (const float*)d_in[0];
    const int*   ei  = (const int*)d_in[1];
    const float* W1  = (const float*)d_in[2];
    const float* b1  = (const float*)d_in[3];
    const float* W2  = (const float*)d_in[4];
    const float* b2  = (const float*)d_in[5];
    const float* Wf  = (const float*)d_in[6];
    const float* bf  = (const float*)d_in[7];
    float* out = (float*)d_out;

    const int TB = 256;
    int gE = (N_EDGES + TB - 1) / TB;        // 12500 (== N_NODES*32/256)
    int gW = (N_NODES * 32 + TB - 1) / TB;
    int gT = (N_NODES + 15) / 16;

    k_initcount<<<gE, TB>>>(x, ei);
    k_scan1<<<NB_SCAN, 256>>>();
    k_scan2<<<1, 512>>>();
    k_scan3<<<NB_SCAN, 256>>>();
    k_scatter<<<gE, TB>>>(ei);

    k_agg1<<<gW, TB>>>();
    k_xform12<<<gT, TB>>>(W1, b1, W2);
    k_agg2f<<<gW, TB>>>(b2, Wf, bf, out);
}

// round 8
// speedup vs baseline: 1.9429x; 1.0615x over previous
#include <cuda_runtime.h>
#include <cuda_fp16.h>

#define N_NODES 100000
#define N_EDGES 3200000
#define NB_SCAN 391            // ceil(N_NODES/256)

// ---------------- scratch ----------------
__device__ int    g_is64;
__device__ int    g_count[N_NODES];      // re-zeroed by k_scan3 each run
__device__ int    g_part[NB_SCAN];
__device__ int    g_partoff[NB_SCAN];
__device__ int    g_off[N_NODES + 1];
__device__ int    g_cursor[N_NODES];
__device__ float  g_dinv[N_NODES];
__device__ int    g_src[N_EDGES];        // CSR src only (4B/edge)
__device__ __half g_x16[N_NODES * 32];   // x padded 22->32 fp16; scaled by dinv in k_scatter
__device__ float  g_aggX[N_NODES * 32];  // aggregated raw features (fp32)
__device__ __half g_h16[N_NODES * 64];   // layer-2 agg input, PRE-SCALED by dinv[node]

// ---------------- fused init: pad x, detect dtype, count degrees ----------------
__global__ void k_initcount(const float* __restrict__ x, const int* __restrict__ ei32) {
    __shared__ int s_is64;
    int t = threadIdx.x;
    if (t < 32) {
        int any = ei32[2 * t + 1] | ei32[2 * (t + 32) + 1];
        for (int off = 16; off; off >>= 1) any |= __shfl_xor_sync(0xffffffffu, any, off);
        if (t == 0) {
            s_is64 = (any == 0) ? 1 : 0;
            if (blockIdx.x == 0) g_is64 = s_is64;
        }
    }
    int i = blockIdx.x * blockDim.x + t;
    if (i < N_NODES * 32) {
        int n = i >> 5, c = i & 31;
        g_x16[i] = __float2half_rn((c < 22) ? x[n * 22 + c] : 0.f);   // unscaled for now
    }
    __syncthreads();
    int is64 = s_is64;
    int d = is64 ? ei32[2 * (N_EDGES + i)] : ei32[N_EDGES + i];
    if ((unsigned)d < N_NODES) atomicAdd(&g_count[d], 1);
}

// scan phase 1: per-block partial sums + dinv
__global__ void k_scan1() {
    __shared__ int red[256];
    int t = threadIdx.x;
    int i = blockIdx.x * 256 + t;
    int c = (i < N_NODES) ? g_count[i] : 0;
    if (i < N_NODES) g_dinv[i] = rsqrtf((float)c + 1.0f);
    red[t] = c;
    __syncthreads();
    for (int off = 128; off; off >>= 1) {
        if (t < off) red[t] += red[t + off];
        __syncthreads();
    }
    if (t == 0) g_part[blockIdx.x] = red[0];
}

// scan phase 2: warp-shuffle scan of NB_SCAN partials (exclusive)
__global__ void k_scan2() {
    __shared__ int wsum[16];
    int t = threadIdx.x;            // 512 threads
    int lane = t & 31, wid = t >> 5;
    int v = (t < NB_SCAN) ? g_part[t] : 0;
    int s = v;
#pragma unroll
    for (int off = 1; off < 32; off <<= 1) {
        int u = __shfl_up_sync(0xffffffffu, s, off);
        if (lane >= off) s += u;
    }
    if (lane == 31) wsum[wid] = s;
    __syncthreads();
    if (wid == 0) {
        int ws = (lane < 16) ? wsum[lane] : 0;
#pragma unroll
        for (int off = 1; off < 16; off <<= 1) {
            int u = __shfl_up_sync(0xffffffffu, ws, off);
            if (lane >= off) ws += u;
        }
        if (lane < 16) wsum[lane] = ws;
    }
    __syncthreads();
    int incl = s + (wid > 0 ? wsum[wid - 1] : 0);
    if (t < NB_SCAN) g_partoff[t] = incl - v;
    if (t == 511) g_off[N_NODES] = incl;
}

// scan phase 3: block-local exclusive scan + offset; re-zeroes g_count
__global__ void k_scan3() {
    __shared__ int s[256];
    int t = threadIdx.x;
    int i = blockIdx.x * 256 + t;
    int c = (i < N_NODES) ? g_count[i] : 0;
    s[t] = c;
    __syncthreads();
    for (int off = 1; off < 256; off <<= 1) {
        int u = (t >= off) ? s[t - off] : 0;
        __syncthreads();
        s[t] += u;
        __syncthreads();
    }
    if (i < N_NODES) {
        int excl = s[t] - c + g_partoff[blockIdx.x];
        g_off[i] = excl;
        g_cursor[i] = excl;
        g_count[i] = 0;
    }
}

// scatter (src only) + scale x16 by dinv (same 3.2M-thread grid)
__global__ void k_scatter(const int* __restrict__ ei32) {
    int e = blockIdx.x * blockDim.x + threadIdx.x;
    // scale x16 in place: i>>5 broadcast dinv load per 32 threads
    {
        float dn = g_dinv[e >> 5];
        g_x16[e] = __float2half_rn(__half2float(g_x16[e]) * dn);
    }
    int is64 = g_is64;
    int s = is64 ? ei32[2 * e] : ei32[e];
    int d = is64 ? ei32[2 * (N_EDGES + e)] : ei32[N_EDGES + e];
    if ((unsigned)d < N_NODES && (unsigned)s < N_NODES) {
        int pos = atomicAdd(&g_cursor[d], 1);
        g_src[pos] = s;
    }
}

// aggX[d] = dinv[d] * ( xs[d] + sum_e xs[src_e] );  xs pre-scaled. warp/node.
__global__ void k_agg1() {
    int w = (blockIdx.x * blockDim.x + threadIdx.x) >> 5;
    int lane = threadIdx.x & 31;
    if (w >= N_NODES) return;
    float di = g_dinv[w];
    float a0 = __half2float(g_x16[w * 32 + lane]);
    float a1 = 0.f, a2 = 0.f, a3 = 0.f;
    int lo = g_off[w], hi = g_off[w + 1];
    int base = lo;
    int nfull = (hi - lo) & ~31;
    for (; base < lo + nfull; base += 32) {
        int sv = g_src[base + lane];
#pragma unroll
        for (int j = 0; j < 32; j += 4) {
            int s0 = __shfl_sync(0xffffffffu, sv, j);
            int s1 = __shfl_sync(0xffffffffu, sv, j + 1);
            int s2 = __shfl_sync(0xffffffffu, sv, j + 2);
            int s3 = __shfl_sync(0xffffffffu, sv, j + 3);
            a0 += __half2float(g_x16[s0 * 32 + lane]);
            a1 += __half2float(g_x16[s1 * 32 + lane]);
            a2 += __half2float(g_x16[s2 * 32 + lane]);
            a3 += __half2float(g_x16[s3 * 32 + lane]);
        }
    }
    int rem = hi - base;
    if (rem > 0) {
        int idx = base + lane;
        int sv = (idx < hi) ? g_src[idx] : 0;
        for (int j = 0; j < rem; j++) {
            int sj = __shfl_sync(0xffffffffu, sv, j);
            a0 += __half2float(g_x16[sj * 32 + lane]);
        }
    }
    g_aggX[w * 32 + lane] = di * (a0 + a1 + a2 + a3);
}

// h16 = fp16( dinv[node] * (relu(aggX@W1+b1)@W2) ); 16 nodes / 256-thread block
__global__ void k_xform12(const float* __restrict__ W1, const float* __restrict__ b1,
                          const float* __restrict__ W2) {
    __shared__ float W1s[22 * 64];
    __shared__ float W2s[64 * 64];
    __shared__ float h1s[4 * 64];
    __shared__ float as[4 * 22];
    int t = threadIdx.x;
    for (int i = t; i < 22 * 64; i += 256) W1s[i] = W1[i];
    for (int i = t; i < 64 * 64; i += 256) W2s[i] = W2[i];
    int r = t >> 6, j = t & 63;
    float b1j = b1[j];
#pragma unroll
    for (int p = 0; p < 4; p++) {
        int nb = blockIdx.x * 16 + p * 4;
        __syncthreads();
        for (int i = t; i < 4 * 22; i += 256) {
            int n = nb + i / 22;
            as[i] = (n < N_NODES) ? g_aggX[n * 32 + (i % 22)] : 0.f;
        }
        __syncthreads();
        float a = 0.f;
#pragma unroll
        for (int k = 0; k < 22; k++) a += as[r * 22 + k] * W1s[k * 64 + j];
        h1s[r * 64 + j] = fmaxf(a + b1j, 0.f);
        __syncthreads();
        float acc = 0.f;
#pragma unroll
        for (int k = 0; k < 64; k++) acc += h1s[r * 64 + k] * W2s[k * 64 + j];
        int node = nb + r;
        if (node < N_NODES)
            g_h16[node * 64 + j] = __float2half_rn(acc * g_dinv[node]);
    }
}

// layer-2 agg (pre-scaled fp16 features) fused with head
__global__ void k_agg2f(const float* __restrict__ b2, const float* __restrict__ Wf,
                        const float* __restrict__ bf, float* __restrict__ out) {
    int w = (blockIdx.x * blockDim.x + threadIdx.x) >> 5;
    int lane = threadIdx.x & 31;
    if (w >= N_NODES) return;
    float di = g_dinv[w];
    const __half2* __restrict__ h2 = (const __half2*)g_h16;
    float2 v = __half22float2(h2[w * 32 + lane]);
    float2 acc0 = v;                          // self term (pre-scaled)
    float2 acc1 = make_float2(0.f, 0.f);
    int lo = g_off[w], hi = g_off[w + 1];
    int base = lo;
    int nfull = (hi - lo) & ~31;
    for (; base < lo + nfull; base += 32) {
        int sv = g_src[base + lane];
#pragma unroll
        for (int j = 0; j < 32; j += 2) {
            int s0 = __shfl_sync(0xffffffffu, sv, j);
            int s1 = __shfl_sync(0xffffffffu, sv, j + 1);
            float2 h0 = __half22float2(h2[s0 * 32 + lane]);
            float2 h1 = __half22float2(h2[s1 * 32 + lane]);
            acc0.x += h0.x; acc0.y += h0.y;
            acc1.x += h1.x; acc1.y += h1.y;
        }
    }
    int rem = hi - base;
    if (rem > 0) {
        int idx = base + lane;
        int sv = (idx < hi) ? g_src[idx] : 0;
        for (int j = 0; j < rem; j++) {
            int sj = __shfl_sync(0xffffffffu, sv, j);
            float2 hv = __half22float2(h2[sj * 32 + lane]);
            acc0.x += hv.x; acc0.y += hv.y;
        }
    }
    float ax = di * (acc0.x + acc1.x);
    float ay = di * (acc0.y + acc1.y);
    float r0 = fmaxf(ax + b2[2 * lane], 0.f) * Wf[2 * lane];
    float r1 = fmaxf(ay + b2[2 * lane + 1], 0.f) * Wf[2 * lane + 1];
    float s = r0 + r1;
#pragma unroll
    for (int off = 16; off; off >>= 1) s += __shfl_xor_sync(0xffffffffu, s, off);
    if (lane == 0) out[w] = s + bf[0];
}

// ---------------- launch ----------------
extern "C" void kernel_launch(void* const* d_in, const int* in_sizes, int n_in,
                              void* d_out, int out_size) {
    const float* x   = (const float*)d_in[0];
    const int*   ei  = (const int*)d_in[1];
    const float* W1  = (const float*)d_in[2];
    const float* b1  = (const float*)d_in[3];
    const float* W2  = (const float*)d_in[4];
    const float* b2  = (const float*)d_in[5];
    const float* Wf  = (const float*)d_in[6];
    const float* bf  = (const float*)d_in[7];
    float* out = (float*)d_out;

    const int TB = 256;
    int gE = (N_EDGES + TB - 1) / TB;        // 12500 == N_NODES*32/256
    int gW = (N_NODES * 32 + TB - 1) / TB;
    int gT = (N_NODES + 15) / 16;

    k_initcount<<<gE, TB>>>(x, ei);
    k_scan1<<<NB_SCAN, 256>>>();
    k_scan2<<<1, 512>>>();
    k_scan3<<<NB_SCAN, 256>>>();
    k_scatter<<<gE, TB>>>(ei);

    k_agg1<<<gW, TB>>>();
    k_xform12<<<gT, TB>>>(W1, b1, W2);
    k_agg2f<<<gW, TB>>>(b2, Wf, bf, out);
}